// round 1
// baseline (speedup 1.0000x reference)
#include <cuda_runtime.h>
#include <cstdint>

// Problem constants (B=2, N=8192 -> M=16384, fixed for this problem id)
#define MTOT        16384
#define BSHIFT      13            // N = 8192 per batch
#define K2T         256           // threads per CTA in main kernel
#define ROWS_CTA    512           // rows per CTA (2 rows per thread)
#define NSLICE      16
#define SLICE_J     (MTOT / NSLICE)      // 1024
#define TILE_J      256
#define TILES_SL    (SLICE_J / TILE_J)   // 4
#define K3_WARPS    32
#define K3_CTAS     (MTOT / K3_WARPS)    // 512

typedef unsigned long long ull;

// ---------------- scratch (device globals; no allocations) ----------------
__device__ float4 g_gt[MTOT];              // gx, gy, gz, |g|^2
__device__ float4 g_pr[MTOT];              // -2px, -2py, -2pz, 0
__device__ float2 g_p1[MTOT / 256];        // per-CTA (sum w, sum w*err)
__device__ float  g_pmin[NSLICE][MTOT];    // per-slice min value per row
__device__ int    g_ptile[NSLICE][MTOT];   // per-slice winning (global) tile id
__device__ float4 g_p3[K3_CTAS];           // per-CTA (s0, s1, c0, c1)

// ---------------- packed f32x2 helpers ----------------
__device__ __forceinline__ ull pack2(float lo, float hi) {
    ull r; asm("mov.b64 %0, {%1, %2};" : "=l"(r) : "f"(lo), "f"(hi)); return r;
}
__device__ __forceinline__ float2 unpack2(ull v) {
    float2 r; asm("mov.b64 {%0, %1}, %2;" : "=f"(r.x), "=f"(r.y) : "l"(v)); return r;
}
__device__ __forceinline__ ull fma2(ull a, ull b, ull c) {
    ull d; asm("fma.rn.f32x2 %0, %1, %2, %3;" : "=l"(d) : "l"(a), "l"(b), "l"(c)); return d;
}

// ---------------- kernel 1: prep (gt, |g|^2, -2p, weighted L1 err sums) ----------------
__global__ __launch_bounds__(256) void k_prep(const float* __restrict__ kb,
                                              const float* __restrict__ kw,
                                              const float* __restrict__ pg,
                                              const float* __restrict__ ow) {
    int i = blockIdx.x * 256 + threadIdx.x;
    int b = i >> BSHIFT;
    const float* P = pg + b * 12;
    float x = kb[3 * i], y = kb[3 * i + 1], z = kb[3 * i + 2];
    float gx = P[0] * x + P[1] * y + P[2]  * z + P[3];
    float gy = P[4] * x + P[5] * y + P[6]  * z + P[7];
    float gz = P[8] * x + P[9] * y + P[10] * z + P[11];
    float px = kw[3 * i], py = kw[3 * i + 1], pz = kw[3 * i + 2];
    float sg = gx * gx + gy * gy + gz * gz;
    g_gt[i] = make_float4(gx, gy, gz, sg);
    g_pr[i] = make_float4(-2.0f * px, -2.0f * py, -2.0f * pz, 0.0f);

    float err = fabsf(px - gx) + fabsf(py - gy) + fabsf(pz - gz);
    float w = ow[i];
    float sw = w, swe = w * err;
    #pragma unroll
    for (int off = 16; off; off >>= 1) {
        sw  += __shfl_down_sync(0xffffffffu, sw,  off);
        swe += __shfl_down_sync(0xffffffffu, swe, off);
    }
    __shared__ float sa[8], sb[8];
    int lane = threadIdx.x & 31, wid = threadIdx.x >> 5;
    if (lane == 0) { sa[wid] = sw; sb[wid] = swe; }
    __syncthreads();
    if (threadIdx.x == 0) {
        float A = 0.f, Bv = 0.f;
        #pragma unroll
        for (int k = 0; k < 8; k++) { A += sa[k]; Bv += sb[k]; }
        g_p1[blockIdx.x] = make_float2(A, Bv);
    }
}

// ---------------- kernel 2: main pass — exact min + first-decrease tile ----------------
__global__ __launch_bounds__(K2T, 2) void k_dist() {
    __shared__ __align__(16) float s_gx[SLICE_J];
    __shared__ __align__(16) float s_gy[SLICE_J];
    __shared__ __align__(16) float s_gz[SLICE_J];
    __shared__ __align__(16) float s_ss[SLICE_J];

    int tid = threadIdx.x;
    int jbase = blockIdx.y * SLICE_J;
    for (int k = tid; k < SLICE_J; k += K2T) {
        float4 g = g_gt[jbase + k];
        s_gx[k] = g.x; s_gy[k] = g.y; s_gz[k] = g.z; s_ss[k] = g.w;
    }
    __syncthreads();

    int row0 = blockIdx.x * ROWS_CTA + tid;
    int row1 = row0 + K2T;
    float4 pA = g_pr[row0];
    float4 pB = g_pr[row1];
    ull a0 = pack2(pA.x, pA.x), a1 = pack2(pA.y, pA.y), a2 = pack2(pA.z, pA.z);
    ull b0 = pack2(pB.x, pB.x), b1 = pack2(pB.y, pB.y), b2 = pack2(pB.z, pB.z);

    const float INF = __int_as_float(0x7f800000);
    float accA[4], accB[4];
    #pragma unroll
    for (int q = 0; q < 4; q++) { accA[q] = INF; accB[q] = INF; }
    float bestA = INF, bestB = INF;
    int tA = 0, tB = 0;

    #pragma unroll 1
    for (int t = 0; t < TILES_SL; t++) {
        #pragma unroll 4
        for (int js = t * TILE_J; js < (t + 1) * TILE_J; js += 8) {
            ulonglong2 X0 = *(const ulonglong2*)(s_gx + js);
            ulonglong2 X1 = *(const ulonglong2*)(s_gx + js + 4);
            ulonglong2 Y0 = *(const ulonglong2*)(s_gy + js);
            ulonglong2 Y1 = *(const ulonglong2*)(s_gy + js + 4);
            ulonglong2 Z0 = *(const ulonglong2*)(s_gz + js);
            ulonglong2 Z1 = *(const ulonglong2*)(s_gz + js + 4);
            ulonglong2 S0 = *(const ulonglong2*)(s_ss + js);
            ulonglong2 S1 = *(const ulonglong2*)(s_ss + js + 4);
            ull gx[4] = {X0.x, X0.y, X1.x, X1.y};
            ull gy[4] = {Y0.x, Y0.y, Y1.x, Y1.y};
            ull gz[4] = {Z0.x, Z0.y, Z1.x, Z1.y};
            ull sq[4] = {S0.x, S0.y, S1.x, S1.y};
            #pragma unroll
            for (int q = 0; q < 4; q++) {
                ull dA = fma2(a0, gx[q], fma2(a1, gy[q], fma2(a2, gz[q], sq[q])));
                float2 uA = unpack2(dA);
                accA[q] = fminf(accA[q], fminf(uA.x, uA.y));
                ull dB = fma2(b0, gx[q], fma2(b1, gy[q], fma2(b2, gz[q], sq[q])));
                float2 uB = unpack2(dB);
                accB[q] = fminf(accB[q], fminf(uB.x, uB.y));
            }
        }
        float mA = fminf(fminf(accA[0], accA[1]), fminf(accA[2], accA[3]));
        float mB = fminf(fminf(accB[0], accB[1]), fminf(accB[2], accB[3]));
        int gtile = blockIdx.y * TILES_SL + t;
        if (mA < bestA) { bestA = mA; tA = gtile; }
        if (mB < bestB) { bestB = mB; tB = gtile; }
    }
    g_pmin[blockIdx.y][row0] = bestA;  g_ptile[blockIdx.y][row0] = tA;
    g_pmin[blockIdx.y][row1] = bestB;  g_ptile[blockIdx.y][row1] = tB;
}

// ---------------- kernel 3: merge slices, rescan winning tile, BCE ----------------
__global__ __launch_bounds__(K3_WARPS * 32) void k_argmin_bce(const float* __restrict__ logits) {
    int tid = threadIdx.x, lane = tid & 31, wid = tid >> 5;
    int row = blockIdx.x * K3_WARPS + wid;

    float v = __int_as_float(0x7f800000);
    int tl = 0x7fffffff;
    if (lane < NSLICE) { v = g_pmin[lane][row]; tl = g_ptile[lane][row]; }
    #pragma unroll
    for (int off = 16; off; off >>= 1) {
        float v2 = __shfl_down_sync(0xffffffffu, v, off);
        int   t2 = __shfl_down_sync(0xffffffffu, tl, off);
        if (v2 < v || (v2 == v && t2 < tl)) { v = v2; tl = t2; }
    }
    v  = __shfl_sync(0xffffffffu, v, 0);
    tl = __shfl_sync(0xffffffffu, tl, 0);

    float4 pr = g_pr[row];
    ull a0 = pack2(pr.x, pr.x), a1 = pack2(pr.y, pr.y), a2 = pack2(pr.z, pr.z);

    int cand = 0x7fffffff;
    int jb = tl * TILE_J;
    #pragma unroll
    for (int k = 0; k < TILE_J / 64; k++) {
        int j = jb + 2 * (k * 32 + lane);
        float4 gA = g_gt[j];
        float4 gB = g_gt[j + 1];
        ull d = fma2(a0, pack2(gA.x, gB.x),
                fma2(a1, pack2(gA.y, gB.y),
                fma2(a2, pack2(gA.z, gB.z), pack2(gA.w, gB.w))));
        float2 u = unpack2(d);
        if (u.x == v) cand = min(cand, j);
        if (u.y == v) cand = min(cand, j + 1);
    }
    #pragma unroll
    for (int off = 16; off; off >>= 1)
        cand = min(cand, __shfl_down_sync(0xffffffffu, cand, off));

    __shared__ float s0s[K3_WARPS], s1s[K3_WARPS], c0s[K3_WARPS], c1s[K3_WARPS];
    if (lane == 0) {
        bool m = (cand == row);                 // knn_ind[row] == row
        float x = logits[row];
        float ax = fabsf(x);
        float lp = log1pf(expf(-ax));
        float spx = fmaxf(x, 0.f) + lp;         // softplus(x)
        float spn = fmaxf(-x, 0.f) + lp;        // softplus(-x)
        float bce = m ? spn : spx;
        s1s[wid] = m ? bce : 0.f;  s0s[wid] = m ? 0.f : bce;
        c1s[wid] = m ? 1.f : 0.f;  c0s[wid] = m ? 0.f : 1.f;
    }
    __syncthreads();
    if (tid < 32) {
        float s0 = s0s[tid], s1 = s1s[tid], c0 = c0s[tid], c1 = c1s[tid];
        #pragma unroll
        for (int off = 16; off; off >>= 1) {
            s0 += __shfl_down_sync(0xffffffffu, s0, off);
            s1 += __shfl_down_sync(0xffffffffu, s1, off);
            c0 += __shfl_down_sync(0xffffffffu, c0, off);
            c1 += __shfl_down_sync(0xffffffffu, c1, off);
        }
        if (tid == 0) g_p3[blockIdx.x] = make_float4(s0, s1, c0, c1);
    }
}

// ---------------- kernel 4: final deterministic reduction ----------------
__global__ __launch_bounds__(512) void k_final(float* __restrict__ out) {
    __shared__ float4 sm[K3_CTAS];
    __shared__ float2 sm2[MTOT / 256];
    int t = threadIdx.x;
    sm[t] = g_p3[t];
    if (t < MTOT / 256) sm2[t] = g_p1[t];
    __syncthreads();
    for (int s = K3_CTAS / 2; s >= 1; s >>= 1) {
        if (t < s) {
            float4 a = sm[t], b = sm[t + s];
            sm[t] = make_float4(a.x + b.x, a.y + b.y, a.z + b.z, a.w + b.w);
        }
        __syncthreads();
    }
    for (int s = MTOT / 512; s >= 1; s >>= 1) {
        if (t < s) {
            float2 a = sm2[t], b = sm2[t + s];
            sm2[t] = make_float2(a.x + b.x, a.y + b.y);
        }
        __syncthreads();
    }
    if (t == 0) {
        float4 r = sm[0];       // s0, s1, c0, c1
        float2 q = sm2[0];      // sum_w, sum_w_err
        float mean_err = q.y / fmaxf(q.x, 1e-6f);
        float g0 = (r.z > 0.f) ? (r.x / fmaxf(r.z, 1.f)) : 0.f;
        float g1 = (r.w > 0.f) ? (r.y / fmaxf(r.w, 1.f)) : 0.f;
        out[0] = mean_err + 0.5f * g0 + 0.5f * g1;
    }
}

// ---------------- launch ----------------
extern "C" void kernel_launch(void* const* d_in, const int* in_sizes, int n_in,
                              void* d_out, int out_size) {
    const float* kb = (const float*)d_in[0];   // kp_before       (B,N,3)
    const float* kw = (const float*)d_in[1];   // kp_warped_pred  (B,N,3)
    const float* pg = (const float*)d_in[2];   // pose_gt         (B,3,4)
    const float* ow = (const float*)d_in[3];   // overlap_weights (B,N)
    const float* lg = (const float*)d_in[4];   // inlier_logits   (B,N)
    float* out = (float*)d_out;

    k_prep<<<MTOT / 256, 256>>>(kb, kw, pg, ow);
    dim3 g2(MTOT / ROWS_CTA, NSLICE);
    k_dist<<<g2, K2T>>>();
    k_argmin_bce<<<K3_CTAS, K3_WARPS * 32>>>(lg);
    k_final<<<1, 512>>>(out);
}

// round 2
// speedup vs baseline: 3.3767x; 3.3767x over previous
#include <cuda_runtime.h>

// Problem constants (B=2, N=8192 -> M=16384, fixed for this problem id)
#define MTOT      16384
#define BSHIFT    13
#define NCAND     256            // candidates tested per row in phase A
#define PA_CTAS   (MTOT / 256)   // 64
#define FB_CTAS   128
#define FB_THR    256

// ---------------- scratch (device globals; no allocations) ----------------
__device__ float4 g_gt[MTOT];        // gx, gy, gz, |g|^2
__device__ float4 g_pr[MTOT];        // -2px, -2py, -2pz, 0
__device__ float  g_fown[MTOT];      // f_ii = sg_i - 2 p_i.g_i (canonical fma chain)
__device__ float2 g_p1[PA_CTAS];     // per-CTA (sum w, sum w*err)
__device__ float2 g_pA[PA_CTAS];     // per-CTA (sum bce label0, count label0) resolved rows
__device__ int    g_slist[MTOT];     // survivor rows
__device__ int    g_scnt;            // survivor count
__device__ float  g_fb[4];           // fallback sums: s0, s1, c0, c1

__device__ __forceinline__ float fchain(float4 pr, float4 g) {
    // canonical expression: f = sg + (-2p).g   (must be identical everywhere)
    return fmaf(pr.x, g.x, fmaf(pr.y, g.y, fmaf(pr.z, g.z, g.w)));
}

// ---------------- kernel 1: prep ----------------
__global__ __launch_bounds__(256) void k_prep(const float* __restrict__ kb,
                                              const float* __restrict__ kw,
                                              const float* __restrict__ pg,
                                              const float* __restrict__ ow) {
    int i = blockIdx.x * 256 + threadIdx.x;
    if (i == 0) {                       // reset cross-kernel scratch each call
        g_scnt = 0;
        g_fb[0] = 0.f; g_fb[1] = 0.f; g_fb[2] = 0.f; g_fb[3] = 0.f;
    }
    int b = i >> BSHIFT;
    const float* P = pg + b * 12;
    float x = kb[3 * i], y = kb[3 * i + 1], z = kb[3 * i + 2];
    float gx = P[0] * x + P[1] * y + P[2]  * z + P[3];
    float gy = P[4] * x + P[5] * y + P[6]  * z + P[7];
    float gz = P[8] * x + P[9] * y + P[10] * z + P[11];
    float px = kw[3 * i], py = kw[3 * i + 1], pz = kw[3 * i + 2];
    float sg = gx * gx + gy * gy + gz * gz;
    float4 gt = make_float4(gx, gy, gz, sg);
    float4 pr = make_float4(-2.0f * px, -2.0f * py, -2.0f * pz, 0.0f);
    g_gt[i] = gt;
    g_pr[i] = pr;
    g_fown[i] = fchain(pr, gt);

    float err = fabsf(px - gx) + fabsf(py - gy) + fabsf(pz - gz);
    float w = ow[i];
    float sw = w, swe = w * err;
    #pragma unroll
    for (int off = 16; off; off >>= 1) {
        sw  += __shfl_down_sync(0xffffffffu, sw,  off);
        swe += __shfl_down_sync(0xffffffffu, swe, off);
    }
    __shared__ float sa[8], sb[8];
    int lane = threadIdx.x & 31, wid = threadIdx.x >> 5;
    if (lane == 0) { sa[wid] = sw; sb[wid] = swe; }
    __syncthreads();
    if (threadIdx.x == 0) {
        float A = 0.f, Bv = 0.f;
        #pragma unroll
        for (int k = 0; k < 8; k++) { A += sa[k]; Bv += sb[k]; }
        g_p1[blockIdx.x] = make_float2(A, Bv);
    }
}

// ---------------- kernel 2: phase A — resolve mask=0 rows via 256 shared candidates ----------------
__global__ __launch_bounds__(256) void k_phaseA(const float* __restrict__ logits) {
    __shared__ __align__(16) float4 s_c[NCAND];
    __shared__ float ss[8], sc[8];
    int tid = threadIdx.x;

    // CTA-shared candidate set (distinct: odd multiplier mod 2^14 is a bijection)
    unsigned h = blockIdx.x * 1664525u + 1013904223u;
    if (tid < NCAND) {
        unsigned j = (h + (unsigned)tid * 2654435761u) & (MTOT - 1);
        s_c[tid] = g_gt[j];
    }
    __syncthreads();

    int row = blockIdx.x * 256 + tid;
    float4 pr = g_pr[row];
    float fo = g_fown[row];

    const float INF = __int_as_float(0x7f800000);
    float m0 = INF, m1 = INF, m2 = INF, m3 = INF;
    #pragma unroll 4
    for (int k = 0; k < NCAND; k += 4) {
        m0 = fminf(m0, fchain(pr, s_c[k + 0]));
        m1 = fminf(m1, fchain(pr, s_c[k + 1]));
        m2 = fminf(m2, fchain(pr, s_c[k + 2]));
        m3 = fminf(m3, fchain(pr, s_c[k + 3]));
    }
    float mn = fminf(fminf(m0, m1), fminf(m2, m3));
    bool resolved = (mn < fo);    // some candidate strictly closer -> mask = 0

    float s0 = 0.f, c0 = 0.f;
    if (resolved) {
        float xv = logits[row];
        float lp = log1pf(expf(-fabsf(xv)));
        s0 = fmaxf(xv, 0.f) + lp;          // softplus(x), label 0
        c0 = 1.f;
    } else {
        int pos = atomicAdd(&g_scnt, 1);
        g_slist[pos] = row;
    }

    #pragma unroll
    for (int off = 16; off; off >>= 1) {
        s0 += __shfl_down_sync(0xffffffffu, s0, off);
        c0 += __shfl_down_sync(0xffffffffu, c0, off);
    }
    int lane = tid & 31, wid = tid >> 5;
    if (lane == 0) { ss[wid] = s0; sc[wid] = c0; }
    __syncthreads();
    if (tid == 0) {
        float A = 0.f, C = 0.f;
        #pragma unroll
        for (int k = 0; k < 8; k++) { A += ss[k]; C += sc[k]; }
        g_pA[blockIdx.x] = make_float2(A, C);
    }
}

// ---------------- kernel 3: fallback — exact full-row scan for survivors ----------------
__global__ __launch_bounds__(FB_THR) void k_fb(const float* __restrict__ logits) {
    __shared__ float s_mn[FB_THR / 32];
    int S = g_scnt;
    const float INF = __int_as_float(0x7f800000);

    for (int s = blockIdx.x; s < S; s += FB_CTAS) {
        int row = g_slist[s];
        float4 pr = g_pr[row];
        float a0 = INF, a1 = INF;
        // 16384 / 256 = 64 j's per thread, 2 independent chains
        for (int j = threadIdx.x; j < MTOT; j += 2 * FB_THR) {
            a0 = fminf(a0, fchain(pr, g_gt[j]));
            a1 = fminf(a1, fchain(pr, g_gt[j + FB_THR]));
        }
        float mn = fminf(a0, a1);
        #pragma unroll
        for (int off = 16; off; off >>= 1)
            mn = fminf(mn, __shfl_down_sync(0xffffffffu, mn, off));
        int lane = threadIdx.x & 31, wid = threadIdx.x >> 5;
        if (lane == 0) s_mn[wid] = mn;
        __syncthreads();
        if (threadIdx.x == 0) {
            float m = s_mn[0];
            #pragma unroll
            for (int k = 1; k < FB_THR / 32; k++) m = fminf(m, s_mn[k]);
            // mn includes j==row via the identical fma chain -> mn <= f_own always;
            // equality  <=>  no strictly closer point  <=>  mask = 1
            bool mask = (g_fown[row] <= m);
            float xv = logits[row];
            float lp = log1pf(expf(-fabsf(xv)));
            if (mask) {
                atomicAdd(&g_fb[1], fmaxf(-xv, 0.f) + lp);   // softplus(-x), label 1
                atomicAdd(&g_fb[3], 1.f);
            } else {
                atomicAdd(&g_fb[0], fmaxf(xv, 0.f) + lp);
                atomicAdd(&g_fb[2], 1.f);
            }
        }
        __syncthreads();
    }
}

// ---------------- kernel 4: final reduction ----------------
__global__ __launch_bounds__(32) void k_final(float* __restrict__ out) {
    int t = threadIdx.x;
    float2 a0 = g_p1[t], a1 = g_p1[t + 32];
    float2 b0 = g_pA[t], b1 = g_pA[t + 32];
    float sw  = a0.x + a1.x;
    float swe = a0.y + a1.y;
    float s0  = b0.x + b1.x;
    float c0  = b0.y + b1.y;
    #pragma unroll
    for (int off = 16; off; off >>= 1) {
        sw  += __shfl_down_sync(0xffffffffu, sw,  off);
        swe += __shfl_down_sync(0xffffffffu, swe, off);
        s0  += __shfl_down_sync(0xffffffffu, s0,  off);
        c0  += __shfl_down_sync(0xffffffffu, c0,  off);
    }
    if (t == 0) {
        s0 += g_fb[0];
        c0 += g_fb[2];
        float s1 = g_fb[1];
        float c1 = g_fb[3];
        float mean_err = swe / fmaxf(sw, 1e-6f);
        float gr0 = (c0 > 0.f) ? (s0 / fmaxf(c0, 1.f)) : 0.f;
        float gr1 = (c1 > 0.f) ? (s1 / fmaxf(c1, 1.f)) : 0.f;
        out[0] = mean_err + 0.5f * gr0 + 0.5f * gr1;
    }
}

// ---------------- launch ----------------
extern "C" void kernel_launch(void* const* d_in, const int* in_sizes, int n_in,
                              void* d_out, int out_size) {
    const float* kb = (const float*)d_in[0];   // kp_before       (B,N,3)
    const float* kw = (const float*)d_in[1];   // kp_warped_pred  (B,N,3)
    const float* pg = (const float*)d_in[2];   // pose_gt         (B,3,4)
    const float* ow = (const float*)d_in[3];   // overlap_weights (B,N)
    const float* lg = (const float*)d_in[4];   // inlier_logits   (B,N)
    float* out = (float*)d_out;

    k_prep<<<MTOT / 256, 256>>>(kb, kw, pg, ow);
    k_phaseA<<<PA_CTAS, 256>>>(lg);
    k_fb<<<FB_CTAS, FB_THR>>>(lg);
    k_final<<<1, 32>>>(out);
}